// round 4
// baseline (speedup 1.0000x reference)
#include <cuda_runtime.h>

#define M_ROWS 65536
#define T_LEN  16384
#define RC     128
#define NLAYERS 20

// ---------------- device scratch (no runtime allocation allowed) ----------
__device__ float g_res0[(size_t)M_ROWS * RC];
__device__ float g_res1[(size_t)M_ROWS * RC];
__device__ float g_skipacc[(size_t)M_ROWS * RC];

static const int H_DIL[NLAYERS] = {1,2,4,8,16,32,64,128,256,512,
                                   1,2,4,8,16,32,64,128,256,512};

// ---------------- helpers --------------------------------------------------
__device__ __forceinline__ float fast_tanhf(float x) {
    float ax = fabsf(x);
    float e  = __expf(-2.0f * ax);                 // in (0,1], never overflows
    float r  = __fdividef(1.0f - e, 1.0f + e);     // denom in [1,2]
    return copysignf(r, x);
}
__device__ __forceinline__ float fast_sigmoidf(float x) {
    return 0.5f * fast_tanhf(0.5f * x) + 0.5f;
}
__device__ __forceinline__ void fma4(float4& acc, float a, const float4& w) {
    acc.x += a * w.x; acc.y += a * w.y; acc.z += a * w.z; acc.w += a * w.w;
}
__device__ __forceinline__ float comp(const float4& v, int j) {
    return j == 0 ? v.x : j == 1 ? v.y : j == 2 ? v.z : v.w;
}
__device__ __forceinline__ float4 add4(float4 a, const float4& b) {
    a.x += b.x; a.y += b.y; a.z += b.z; a.w += b.w; return a;
}

// ---------------- init causal conv: k=32, 64ch -> 128ch --------------------
// y[t] = sum_{tap=0}^{31} X[t-31+tap] @ W[tap] + b
// smem: As[96 rows x 64ch] (24.5KB) + Ws[64k x 128n] (32KB) = 57344 B
__global__ __launch_bounds__(256, 2)
void k_init(const float* __restrict__ X, const float* __restrict__ W,
            const float* __restrict__ b, float* __restrict__ res)
{
    extern __shared__ float sm[];
    float4* As4 = (float4*)sm;                 // [row(95)][16 f4]
    float4* Ws4 = (float4*)(sm + 96 * 64);     // [64][32 f4]
    const int tid = threadIdx.x;
    const int tx = tid & 31, ty = tid >> 5;
    const int n0 = tx * 4, m0 = ty * 8;
    const int t0 = blockIdx.x * 64;
    const int bstart = t0 & ~(T_LEN - 1);

    const float4* X4 = (const float4*)X;
    #pragma unroll
    for (int i = 0; i < 6; i++) {
        int idx = tid + i * 256;
        if (idx < 95 * 16) {
            int j = idx >> 4, c4 = idx & 15;
            int g = t0 - 31 + j;
            float4 v = make_float4(0.f, 0.f, 0.f, 0.f);
            if (g >= bstart) v = X4[(size_t)g * 16 + c4];
            As4[j * 16 + c4] = v;
        }
    }

    float4 acc[8];
    float4 bias = *(const float4*)&b[n0];
    #pragma unroll
    for (int r = 0; r < 8; r++) acc[r] = bias;

    const float4* W4 = (const float4*)W;
    for (int tap = 0; tap < 32; tap++) {
        __syncthreads();
        #pragma unroll
        for (int i = 0; i < 8; i++) {
            int idx = tid + i * 256;               // 0..2047 f4
            int kl = idx >> 5, n4 = idx & 31;
            Ws4[kl * 32 + n4] = W4[(size_t)((tap << 6) + kl) * 32 + n4];
        }
        __syncthreads();
        #pragma unroll
        for (int kk4 = 0; kk4 < 16; kk4++) {
            float4 a[8];
            #pragma unroll
            for (int r = 0; r < 8; r++) a[r] = As4[(m0 + r + tap) * 16 + kk4];
            #pragma unroll
            for (int j = 0; j < 4; j++) {
                float4 w = Ws4[(kk4 * 4 + j) * 32 + tx];
                #pragma unroll
                for (int r = 0; r < 8; r++) fma4(acc[r], comp(a[r], j), w);
            }
        }
    }
    #pragma unroll
    for (int r = 0; r < 8; r++)
        *(float4*)&res[(size_t)(t0 + m0 + r) * RC + n0] = acc[r];
}

// ---------------- fused gated dilated layer --------------------------------
// p   = tanh(A@Wf + fb) * sigmoid(A@Wg + gb),  A = [x(t-d) | x(t)]  (K=256)
// out += p@Ws + sb ;  res_out = res_in + p@Wr + rb
// smem: As[64x256] (64KB, aliased by Ps[64x128] in phase 2) + 2x[32x128] W (32KB)
__global__ __launch_bounds__(256, 2)
void k_layer(const float* __restrict__ rin, float* __restrict__ rout,
             const float* __restrict__ fW, const float* __restrict__ fB,
             const float* __restrict__ gW, const float* __restrict__ gB,
             const float* __restrict__ sW, const float* __restrict__ sB,
             const float* __restrict__ rW, const float* __restrict__ rB,
             float* __restrict__ oacc_g, int d, int first)
{
    extern __shared__ float sm[];
    float4* As4 = (float4*)sm;                 // [m(64)][64 f4]  (k-major inside row)
    float4* Wa4 = (float4*)(sm + 64 * 256);    // 32x32 f4
    float4* Wb4 = Wa4 + 32 * 32;
    const int tid = threadIdx.x;
    const int tx = tid & 31, ty = tid >> 5;
    const int n0 = tx * 4, m0 = ty * 8;
    const int t0 = blockIdx.x * 64;

    // ---- load A tile: k<128 -> x(t-d), k>=128 -> x(t) ----
    #pragma unroll
    for (int i = 0; i < 16; i++) {
        int idx = tid + i * 256;                   // 0..4095 f4
        int m = idx >> 6, c4 = idx & 63;
        int tm = t0 + m;
        float4 v = make_float4(0.f, 0.f, 0.f, 0.f);
        if (c4 < 32) {
            if ((tm & (T_LEN - 1)) >= d)
                v = *(const float4*)&rin[(size_t)(tm - d) * RC + c4 * 4];
        } else {
            v = *(const float4*)&rin[(size_t)tm * RC + (c4 - 32) * 4];
        }
        As4[m * 64 + c4] = v;
    }

    float4 fa[8], ga[8];
    {
        float4 fb4 = *(const float4*)&fB[n0];
        float4 gb4 = *(const float4*)&gB[n0];
        #pragma unroll
        for (int r = 0; r < 8; r++) { fa[r] = fb4; ga[r] = gb4; }
    }

    // ---- phase 1: f/g GEMMs over K=256, weight chunks of 32 ----
    const float4* fW4 = (const float4*)fW;
    const float4* gW4 = (const float4*)gW;
    for (int c = 0; c < 8; c++) {
        __syncthreads();
        #pragma unroll
        for (int i = 0; i < 8; i++) {
            int idx = tid + i * 256;               // 0..2047
            int sel = idx >> 10, e = idx & 1023;
            int kl = e >> 5, n4 = e & 31;
            const float4* src = sel ? gW4 : fW4;
            float4 v = src[(size_t)(c * 32 + kl) * 32 + n4];
            (sel ? Wb4 : Wa4)[kl * 32 + n4] = v;
        }
        __syncthreads();
        #pragma unroll
        for (int kk4 = 0; kk4 < 8; kk4++) {
            float4 a[8];
            #pragma unroll
            for (int r = 0; r < 8; r++) a[r] = As4[(m0 + r) * 64 + c * 8 + kk4];
            #pragma unroll
            for (int j = 0; j < 4; j++) {
                float4 wf = Wa4[(kk4 * 4 + j) * 32 + tx];
                float4 wg = Wb4[(kk4 * 4 + j) * 32 + tx];
                #pragma unroll
                for (int r = 0; r < 8; r++) {
                    float av = comp(a[r], j);
                    fma4(fa[r], av, wf);
                    fma4(ga[r], av, wg);
                }
            }
        }
    }
    __syncthreads();   // everyone done reading As before we alias it with Ps

    // ---- activations; write p into Ps (aliases As) ----
    float4* Ps4 = (float4*)sm;                 // [m(64)][32 f4]
    #pragma unroll
    for (int r = 0; r < 8; r++) {
        float4 p;
        p.x = fast_tanhf(fa[r].x) * fast_sigmoidf(ga[r].x);
        p.y = fast_tanhf(fa[r].y) * fast_sigmoidf(ga[r].y);
        p.z = fast_tanhf(fa[r].z) * fast_sigmoidf(ga[r].z);
        p.w = fast_tanhf(fa[r].w) * fast_sigmoidf(ga[r].w);
        Ps4[(m0 + r) * 32 + tx] = p;
    }

    // ---- phase 2: skip/res GEMMs over K=128 ----
    {
        float4 sb4 = *(const float4*)&sB[n0];
        float4 rb4 = *(const float4*)&rB[n0];
        #pragma unroll
        for (int r = 0; r < 8; r++) { fa[r] = sb4; ga[r] = rb4; }
    }
    const float4* sW4 = (const float4*)sW;
    const float4* rW4 = (const float4*)rW;
    for (int c = 0; c < 4; c++) {
        __syncthreads();                        // also orders Ps writes -> reads
        #pragma unroll
        for (int i = 0; i < 8; i++) {
            int idx = tid + i * 256;
            int sel = idx >> 10, e = idx & 1023;
            int kl = e >> 5, n4 = e & 31;
            const float4* src = sel ? rW4 : sW4;
            float4 v = src[(size_t)(c * 32 + kl) * 32 + n4];
            (sel ? Wb4 : Wa4)[kl * 32 + n4] = v;
        }
        __syncthreads();
        #pragma unroll
        for (int kk4 = 0; kk4 < 8; kk4++) {
            float4 a[8];
            #pragma unroll
            for (int r = 0; r < 8; r++) a[r] = Ps4[(m0 + r) * 32 + c * 8 + kk4];
            #pragma unroll
            for (int j = 0; j < 4; j++) {
                float4 ws = Wa4[(kk4 * 4 + j) * 32 + tx];
                float4 wr = Wb4[(kk4 * 4 + j) * 32 + tx];
                #pragma unroll
                for (int r = 0; r < 8; r++) {
                    float av = comp(a[r], j);
                    fma4(fa[r], av, ws);
                    fma4(ga[r], av, wr);
                }
            }
        }
    }

    // ---- epilogue: res_out = res_in + racc ; out (+)= oacc ----
    #pragma unroll
    for (int r = 0; r < 8; r++) {
        size_t gidx = (size_t)(t0 + m0 + r) * RC + n0;
        float4 ro = *(const float4*)&rin[gidx];
        *(float4*)&rout[gidx] = add4(ga[r], ro);
        float4 ov = fa[r];
        if (!first) ov = add4(ov, *(const float4*)&oacc_g[gidx]);
        *(float4*)&oacc_g[gidx] = ov;
    }
}

// ---------------- fused skip stack ------------------------------------------
// h = relu(out)@W0+b0 ; 31x: h = relu(h)@Wr[i]+br[i] ; y = relu(h)@Wf+bf
// all weights resident in smem (45312 floats = 177KB); thread-per-row.
#define SK_W0   0
#define SK_WR   4096
#define SK_WF   35840
#define SK_B0   44032
#define SK_BR   44064
#define SK_BF   45056
#define SK_TOT  45312

__global__ __launch_bounds__(512)
void k_skip(const float* __restrict__ oacc,
            const float* __restrict__ w0, const float* __restrict__ b0,
            const float* __restrict__ wr, const float* __restrict__ br,
            const float* __restrict__ wf, const float* __restrict__ bf,
            float* __restrict__ y)
{
    extern __shared__ float sm[];
    const int tid = threadIdx.x;
    for (int i = tid; i < 4096;  i += 512) sm[SK_W0 + i] = w0[i];
    for (int i = tid; i < 31744; i += 512) sm[SK_WR + i] = wr[i];
    for (int i = tid; i < 8192;  i += 512) sm[SK_WF + i] = wf[i];
    for (int i = tid; i < 32;    i += 512) sm[SK_B0 + i] = b0[i];
    for (int i = tid; i < 992;   i += 512) sm[SK_BR + i] = br[i];
    for (int i = tid; i < 256;   i += 512) sm[SK_BF + i] = bf[i];
    __syncthreads();

    const int row = blockIdx.x * 512 + tid;

    float h[32];
    #pragma unroll
    for (int c = 0; c < 32; c++) h[c] = sm[SK_B0 + c];

    // stage 1: 128 -> 32
    const float4* in4 = (const float4*)(oacc + (size_t)row * RC);
    const float4* w0_4 = (const float4*)(sm + SK_W0);
    #pragma unroll 4
    for (int k4 = 0; k4 < 32; k4++) {
        float4 x = __ldg(&in4[k4]);
        x.x = fmaxf(x.x, 0.f); x.y = fmaxf(x.y, 0.f);
        x.z = fmaxf(x.z, 0.f); x.w = fmaxf(x.w, 0.f);
        #pragma unroll
        for (int j = 0; j < 4; j++) {
            float xv = comp(x, j);
            #pragma unroll
            for (int c4 = 0; c4 < 8; c4++) {
                float4 w = w0_4[(k4 * 4 + j) * 8 + c4];
                h[c4*4+0] += xv * w.x; h[c4*4+1] += xv * w.y;
                h[c4*4+2] += xv * w.z; h[c4*4+3] += xv * w.w;
            }
        }
    }

    // stage 2: 31x (32 -> 32)
    #pragma unroll 1
    for (int step = 0; step < 31; step++) {
        float hn[32];
        #pragma unroll
        for (int c = 0; c < 32; c++) hn[c] = sm[SK_BR + step * 32 + c];
        const float4* wr4 = (const float4*)(sm + SK_WR + step * 1024);
        #pragma unroll
        for (int k = 0; k < 32; k++) {
            float xv = fmaxf(h[k], 0.f);
            #pragma unroll
            for (int c4 = 0; c4 < 8; c4++) {
                float4 w = wr4[k * 8 + c4];
                hn[c4*4+0] += xv * w.x; hn[c4*4+1] += xv * w.y;
                hn[c4*4+2] += xv * w.z; hn[c4*4+3] += xv * w.w;
            }
        }
        #pragma unroll
        for (int c = 0; c < 32; c++) h[c] = hn[c];
    }

    // stage 3: 32 -> 256
    float rh[32];
    #pragma unroll
    for (int k = 0; k < 32; k++) rh[k] = fmaxf(h[k], 0.f);
    const float4* wf4 = (const float4*)(sm + SK_WF);
    const float4* bf4 = (const float4*)(sm + SK_BF);
    float* yrow = y + (size_t)row * 256;
    #pragma unroll 1
    for (int g = 0; g < 8; g++) {
        float4 acc[8];
        #pragma unroll
        for (int c4 = 0; c4 < 8; c4++) acc[c4] = bf4[g * 8 + c4];
        #pragma unroll
        for (int k = 0; k < 32; k++) {
            float xv = rh[k];
            #pragma unroll
            for (int c4 = 0; c4 < 8; c4++) {
                float4 w = wf4[k * 64 + g * 8 + c4];
                acc[c4].x += xv * w.x; acc[c4].y += xv * w.y;
                acc[c4].z += xv * w.z; acc[c4].w += xv * w.w;
            }
        }
        #pragma unroll
        for (int c4 = 0; c4 < 8; c4++)
            *(float4*)&yrow[g * 32 + c4 * 4] = acc[c4];
    }
}

// ---------------- launch ----------------------------------------------------
extern "C" void kernel_launch(void* const* d_in, const int* in_sizes, int n_in,
                              void* d_out, int out_size)
{
    const float* X      = (const float*)d_in[0];
    const float* init_w = (const float*)d_in[1];
    const float* init_b = (const float*)d_in[2];
    const float* f_w    = (const float*)d_in[3];
    const float* f_b    = (const float*)d_in[4];
    const float* g_w    = (const float*)d_in[5];
    const float* g_b    = (const float*)d_in[6];
    const float* skip_w = (const float*)d_in[7];
    const float* skip_b = (const float*)d_in[8];
    const float* res_w  = (const float*)d_in[9];
    const float* res_b  = (const float*)d_in[10];
    const float* sk0_w  = (const float*)d_in[11];
    const float* sk0_b  = (const float*)d_in[12];
    const float* skr_w  = (const float*)d_in[13];
    const float* skr_b  = (const float*)d_in[14];
    const float* fin_w  = (const float*)d_in[15];
    const float* fin_b  = (const float*)d_in[16];

    float *r0, *r1, *oa;
    cudaGetSymbolAddress((void**)&r0, g_res0);
    cudaGetSymbolAddress((void**)&r1, g_res1);
    cudaGetSymbolAddress((void**)&oa, g_skipacc);

    const int SM_INIT  = 96 * 64 * 4 + 64 * 128 * 4;        // 57344
    const int SM_LAYER = 64 * 256 * 4 + 2 * 32 * 128 * 4;   // 98304
    const int SM_SKIP  = SK_TOT * 4;                        // 181248

    cudaFuncSetAttribute(k_init,  cudaFuncAttributeMaxDynamicSharedMemorySize, SM_INIT);
    cudaFuncSetAttribute(k_layer, cudaFuncAttributeMaxDynamicSharedMemorySize, SM_LAYER);
    cudaFuncSetAttribute(k_skip,  cudaFuncAttributeMaxDynamicSharedMemorySize, SM_SKIP);

    k_init<<<M_ROWS / 64, 256, SM_INIT>>>(X, init_w, init_b, r0);

    const float* rin = r0;
    float* rout = r1;
    for (int i = 0; i < NLAYERS; i++) {
        k_layer<<<M_ROWS / 64, 256, SM_LAYER>>>(
            rin, rout,
            f_w    + (size_t)i * 2 * RC * RC, f_b    + (size_t)i * RC,
            g_w    + (size_t)i * 2 * RC * RC, g_b    + (size_t)i * RC,
            skip_w + (size_t)i * RC * RC,     skip_b + (size_t)i * RC,
            res_w  + (size_t)i * RC * RC,     res_b  + (size_t)i * RC,
            oa, H_DIL[i], (i == 0) ? 1 : 0);
        const float* t = rin; rin = rout; rout = (float*)t;
    }

    k_skip<<<M_ROWS / 512, 512, SM_SKIP>>>(oa, sk0_w, sk0_b, skr_w, skr_b,
                                           fin_w, fin_b, (float*)d_out);
}

// round 6
// speedup vs baseline: 1.6427x; 1.6427x over previous
#include <cuda_runtime.h>
#include <cuda_bf16.h>
#include <cstdint>

#define M_ROWS 65536
#define T_LEN  16384
#define RC     128
#define NLAYERS 20

// ---- smem layout for k_layer_mma (bytes) ----
#define SM_BF     0
#define SM_BG     512
#define SM_BS     1024
#define SM_BR     1536
#define SM_A      2048
#define A_STRIDE  144        // (64+8) bf16 per row -> 4-mod-32 word stride
#define A_PLANE   18432      // 128 * 144
#define SM_W      38912      // 4 planes: Whi0, Wlo0, Whi1, Wlo1
#define W_PLANE   18432
#define SM_P      112640
#define P_STRIDE  272        // (128+8) bf16 per row
#define P_PLANE   34816
#define SM_TOTAL  182272

// ---------------- device scratch ----------------
__device__ float g_res0[(size_t)M_ROWS * RC];
__device__ float g_res1[(size_t)M_ROWS * RC];
__device__ float g_skipacc[(size_t)M_ROWS * RC];
// pre-split weights: [layer][12 tiles][2 planes][8192 bf16], tile = [128n][64k], k contiguous
// tiles: f chunks 0-3, g chunks 0-3, s chunks 0-1, r chunks 0-1
__device__ __nv_bfloat16 g_wprep[(size_t)NLAYERS * 12 * 2 * 8192];

static const int H_DIL[NLAYERS] = {1,2,4,8,16,32,64,128,256,512,
                                   1,2,4,8,16,32,64,128,256,512};

// ---------------- helpers ----------------
__device__ __forceinline__ float fast_tanhf(float x) {
    float ax = fabsf(x);
    float e  = __expf(-2.0f * ax);
    float r  = __fdividef(1.0f - e, 1.0f + e);
    return copysignf(r, x);
}
__device__ __forceinline__ float fast_sigmoidf(float x) {
    return 0.5f * fast_tanhf(0.5f * x) + 0.5f;
}
__device__ __forceinline__ float comp(const float4& v, int j) {
    return j == 0 ? v.x : j == 1 ? v.y : j == 2 ? v.z : v.w;
}
__device__ __forceinline__ void fma4(float4& acc, float a, const float4& w) {
    acc.x += a * w.x; acc.y += a * w.y; acc.z += a * w.z; acc.w += a * w.w;
}
__device__ __forceinline__ uint32_t pack2(__nv_bfloat16 a, __nv_bfloat16 b) {
    return (uint32_t)__bfloat16_as_ushort(a) |
           ((uint32_t)__bfloat16_as_ushort(b) << 16);
}
__device__ __forceinline__ void split_f4(float4 v, uint2& h, uint2& l) {
    float f[4] = {v.x, v.y, v.z, v.w};
    unsigned short hb[4], lb[4];
    #pragma unroll
    for (int e = 0; e < 4; e++) {
        __nv_bfloat16 hh = __float2bfloat16(f[e]);
        hb[e] = __bfloat16_as_ushort(hh);
        lb[e] = __bfloat16_as_ushort(__float2bfloat16(f[e] - __bfloat162float(hh)));
    }
    h.x = (uint32_t)hb[0] | ((uint32_t)hb[1] << 16);
    h.y = (uint32_t)hb[2] | ((uint32_t)hb[3] << 16);
    l.x = (uint32_t)lb[0] | ((uint32_t)lb[1] << 16);
    l.y = (uint32_t)lb[2] | ((uint32_t)lb[3] << 16);
}
// m16n8k16 row.col bf16 -> f32 accumulate (base PTX, allowed on compute_100)
__device__ __forceinline__ void mma16816(float* c, const uint32_t* a,
                                         uint32_t b0, uint32_t b1) {
    asm volatile(
        "mma.sync.aligned.m16n8k16.row.col.f32.bf16.bf16.f32 "
        "{%0,%1,%2,%3}, {%4,%5,%6,%7}, {%8,%9}, {%0,%1,%2,%3};"
        : "+f"(c[0]), "+f"(c[1]), "+f"(c[2]), "+f"(c[3])
        : "r"(a[0]), "r"(a[1]), "r"(a[2]), "r"(a[3]), "r"(b0), "r"(b1));
}

// ---------------- weight pre-split: fp32 [k][n] -> bf16 hi/lo [n][64k] -----
__global__ void k_prep(const float* __restrict__ fW, const float* __restrict__ gW,
                       const float* __restrict__ sW, const float* __restrict__ rW)
{
    const int bt = blockIdx.x;            // layer*12 + tile
    const int layer = bt / 12, tl = bt % 12;
    const float* src; int K0;
    if (tl < 4)       { src = fW + (size_t)layer * 2 * RC * RC; K0 = tl * 64; }
    else if (tl < 8)  { src = gW + (size_t)layer * 2 * RC * RC; K0 = (tl - 4) * 64; }
    else if (tl < 10) { src = sW + (size_t)layer * RC * RC;     K0 = (tl - 8) * 64; }
    else              { src = rW + (size_t)layer * RC * RC;     K0 = (tl - 10) * 64; }
    uint32_t* hi_p = (uint32_t*)(g_wprep + (size_t)bt * 2 * 8192);
    uint32_t* lo_p = hi_p + 4096 / 2 * 2;         // +8192 bf16 = +4096 u32
    #pragma unroll
    for (int i = 0; i < 16; i++) {
        int u2 = threadIdx.x + i * 256;           // 0..4095 (pairs)
        int n = u2 >> 5, k2 = u2 & 31;
        float w0 = src[(size_t)(K0 + k2 * 2)     * RC + n];
        float w1 = src[(size_t)(K0 + k2 * 2 + 1) * RC + n];
        __nv_bfloat16 h0 = __float2bfloat16(w0), h1 = __float2bfloat16(w1);
        __nv_bfloat16 l0 = __float2bfloat16(w0 - __bfloat162float(h0));
        __nv_bfloat16 l1 = __float2bfloat16(w1 - __bfloat162float(h1));
        hi_p[u2] = pack2(h0, h1);
        lo_p[u2] = pack2(l0, l1);
    }
}

// ---------------- init causal conv (FFMA, unchanged from R1) ----------------
__global__ __launch_bounds__(256, 2)
void k_init(const float* __restrict__ X, const float* __restrict__ W,
            const float* __restrict__ b, float* __restrict__ res)
{
    extern __shared__ float sm[];
    float4* As4 = (float4*)sm;
    float4* Ws4 = (float4*)(sm + 96 * 64);
    const int tid = threadIdx.x;
    const int tx = tid & 31, ty = tid >> 5;
    const int n0 = tx * 4, m0 = ty * 8;
    const int t0 = blockIdx.x * 64;
    const int bstart = t0 & ~(T_LEN - 1);

    const float4* X4 = (const float4*)X;
    #pragma unroll
    for (int i = 0; i < 6; i++) {
        int idx = tid + i * 256;
        if (idx < 95 * 16) {
            int j = idx >> 4, c4 = idx & 15;
            int g = t0 - 31 + j;
            float4 v = make_float4(0.f, 0.f, 0.f, 0.f);
            if (g >= bstart) v = X4[(size_t)g * 16 + c4];
            As4[j * 16 + c4] = v;
        }
    }
    float4 acc[8];
    float4 bias = *(const float4*)&b[n0];
    #pragma unroll
    for (int r = 0; r < 8; r++) acc[r] = bias;
    const float4* W4 = (const float4*)W;
    for (int tap = 0; tap < 32; tap++) {
        __syncthreads();
        #pragma unroll
        for (int i = 0; i < 8; i++) {
            int idx = tid + i * 256;
            int kl = idx >> 5, n4 = idx & 31;
            Ws4[kl * 32 + n4] = W4[(size_t)((tap << 6) + kl) * 32 + n4];
        }
        __syncthreads();
        #pragma unroll
        for (int kk4 = 0; kk4 < 16; kk4++) {
            float4 a[8];
            #pragma unroll
            for (int r = 0; r < 8; r++) a[r] = As4[(m0 + r + tap) * 16 + kk4];
            #pragma unroll
            for (int j = 0; j < 4; j++) {
                float4 w = Ws4[(kk4 * 4 + j) * 32 + tx];
                #pragma unroll
                for (int r = 0; r < 8; r++) fma4(acc[r], comp(a[r], j), w);
            }
        }
    }
    #pragma unroll
    for (int r = 0; r < 8; r++)
        *(float4*)&res[(size_t)(t0 + m0 + r) * RC + n0] = acc[r];
}

// ---------------- tensor-core gated layer (mma.sync bf16 x3) ----------------
__global__ __launch_bounds__(512, 1)
void k_layer_mma(const float* __restrict__ rin, float* __restrict__ rout,
                 const __nv_bfloat16* __restrict__ wp,
                 const float* __restrict__ fB, const float* __restrict__ gB,
                 const float* __restrict__ sB, const float* __restrict__ rB,
                 float* __restrict__ oacc, int d, int first)
{
    extern __shared__ char smem[];
    const int tid = threadIdx.x, wid = tid >> 5, lane = tid & 31;
    const int gr = lane >> 2, cl = lane & 3;
    const int m0 = (wid >> 2) * 32, n0 = (wid & 3) * 32;
    const int t0 = blockIdx.x * 128;
    const int trel = t0 & (T_LEN - 1);

    if (tid < 128) {
        ((float*)(smem + SM_BF))[tid] = fB[tid];
        ((float*)(smem + SM_BG))[tid] = gB[tid];
        ((float*)(smem + SM_BS))[tid] = sB[tid];
        ((float*)(smem + SM_BR))[tid] = rB[tid];
    }

    float accA[2][4][4], accB[2][4][4];   // F,G then S,R
    #pragma unroll
    for (int mr = 0; mr < 2; mr++)
        #pragma unroll
        for (int nc = 0; nc < 4; nc++)
            #pragma unroll
            for (int e = 0; e < 4; e++) { accA[mr][nc][e] = 0.f; accB[mr][nc][e] = 0.f; }

    const uint4* wp4 = (const uint4*)wp;

    // ======== phase 1: F = A@Wf, G = A@Wg over K=256 (4 chunks of 64) ======
    for (int c = 0; c < 4; c++) {
        __syncthreads();
        // stage A chunk (fp32 -> bf16 hi/lo)
        #pragma unroll
        for (int i = 0; i < 4; i++) {
            int idx = tid + i * 512;              // 0..2047 float4 slots
            int m = idx >> 4, q = idx & 15;
            int kg = c * 64 + q * 4;
            int tm = t0 + m;
            float4 v = make_float4(0.f, 0.f, 0.f, 0.f);
            if (kg < 128) {
                if (trel + m >= d)
                    v = ((const float4*)rin)[(size_t)(tm - d) * 32 + (kg >> 2)];
            } else {
                v = ((const float4*)rin)[(size_t)tm * 32 + ((kg - 128) >> 2)];
            }
            uint2 h, l; split_f4(v, h, l);
            int off = m * A_STRIDE + q * 8;
            *(uint2*)(smem + SM_A + off) = h;
            *(uint2*)(smem + SM_A + A_PLANE + off) = l;
        }
        // stage W planes: F_hi, F_lo, G_hi, G_lo
        #pragma unroll
        for (int i = 0; i < 8; i++) {
            int idx = tid + i * 512;              // 0..4095 uint4 slots
            int pl = idx >> 10, u = idx & 1023;
            int tile = (pl >> 1) ? (4 + c) : c;
            int plane = pl & 1;
            uint4 v = wp4[(size_t)(tile * 2 + plane) * 1024 + u];
            int n = u >> 3, kq = u & 7;
            *(uint4*)(smem + SM_W + pl * W_PLANE + n * A_STRIDE + kq * 16) = v;
        }
        __syncthreads();
        #pragma unroll
        for (int ks = 0; ks < 4; ks++) {
            uint32_t ah[2][4], al[2][4];
            #pragma unroll
            for (int mr = 0; mr < 2; mr++) {
                int base = SM_A + (m0 + mr * 16 + gr) * A_STRIDE + ks * 32 + cl * 4;
                ah[mr][0] = *(const uint32_t*)(smem + base);
                ah[mr][1] = *(const uint32_t*)(smem + base + 8 * A_STRIDE);
                ah[mr][2] = *(const uint32_t*)(smem + base + 16);
                ah[mr][3] = *(const uint32_t*)(smem + base + 8 * A_STRIDE + 16);
                al[mr][0] = *(const uint32_t*)(smem + base + A_PLANE);
                al[mr][1] = *(const uint32_t*)(smem + base + A_PLANE + 8 * A_STRIDE);
                al[mr][2] = *(const uint32_t*)(smem + base + A_PLANE + 16);
                al[mr][3] = *(const uint32_t*)(smem + base + A_PLANE + 8 * A_STRIDE + 16);
            }
            #pragma unroll
            for (int mat = 0; mat < 2; mat++) {
                int ph = SM_W + (mat * 2) * W_PLANE, plo = ph + W_PLANE;
                #pragma unroll
                for (int nc = 0; nc < 4; nc++) {
                    int wb = (n0 + nc * 8 + gr) * A_STRIDE + ks * 32 + cl * 4;
                    uint32_t bh0 = *(const uint32_t*)(smem + ph + wb);
                    uint32_t bh1 = *(const uint32_t*)(smem + ph + wb + 16);
                    uint32_t bl0 = *(const uint32_t*)(smem + plo + wb);
                    uint32_t bl1 = *(const uint32_t*)(smem + plo + wb + 16);
                    #pragma unroll
                    for (int mr = 0; mr < 2; mr++) {
                        float* cc = mat ? accB[mr][nc] : accA[mr][nc];
                        mma16816(cc, ah[mr], bh0, bh1);
                        mma16816(cc, ah[mr], bl0, bl1);
                        mma16816(cc, al[mr], bh0, bh1);
                    }
                }
            }
        }
    }

    // ======== epilogue 1: gated activation, split P into smem ========
    {
        const float* bFp = (const float*)(smem + SM_BF);
        const float* bGp = (const float*)(smem + SM_BG);
        #pragma unroll
        for (int mr = 0; mr < 2; mr++)
            #pragma unroll
            for (int nc = 0; nc < 4; nc++) {
                int m = m0 + mr * 16 + gr, n = n0 + nc * 8 + cl * 2;
                #pragma unroll
                for (int h = 0; h < 2; h++) {
                    float f0 = accA[mr][nc][h * 2 + 0] + bFp[n];
                    float f1 = accA[mr][nc][h * 2 + 1] + bFp[n + 1];
                    float g0 = accB[mr][nc][h * 2 + 0] + bGp[n];
                    float g1 = accB[mr][nc][h * 2 + 1] + bGp[n + 1];
                    float p0 = fast_tanhf(f0) * fast_sigmoidf(g0);
                    float p1 = fast_tanhf(f1) * fast_sigmoidf(g1);
                    __nv_bfloat16 h0 = __float2bfloat16(p0);
                    __nv_bfloat16 h1 = __float2bfloat16(p1);
                    __nv_bfloat16 l0 = __float2bfloat16(p0 - __bfloat162float(h0));
                    __nv_bfloat16 l1 = __float2bfloat16(p1 - __bfloat162float(h1));
                    int off = (m + h * 8) * P_STRIDE + n * 2;
                    *(uint32_t*)(smem + SM_P + off) = pack2(h0, h1);
                    *(uint32_t*)(smem + SM_P + P_PLANE + off) = pack2(l0, l1);
                }
            }
    }
    #pragma unroll
    for (int mr = 0; mr < 2; mr++)
        #pragma unroll
        for (int nc = 0; nc < 4; nc++)
            #pragma unroll
            for (int e = 0; e < 4; e++) { accA[mr][nc][e] = 0.f; accB[mr][nc][e] = 0.f; }

    // ======== phase 2: S = P@Ws, R = P@Wr over K=128 (2 chunks) ========
    for (int c2 = 0; c2 < 2; c2++) {
        __syncthreads();
        #pragma unroll
        for (int i = 0; i < 8; i++) {
            int idx = tid + i * 512;
            int pl = idx >> 10, u = idx & 1023;
            int tile = (pl >> 1) ? (10 + c2) : (8 + c2);
            int plane = pl & 1;
            uint4 v = wp4[(size_t)(tile * 2 + plane) * 1024 + u];
            int n = u >> 3, kq = u & 7;
            *(uint4*)(smem + SM_W + pl * W_PLANE + n * A_STRIDE + kq * 16) = v;
        }
        __syncthreads();
        #pragma unroll
        for (int ks = 0; ks < 4; ks++) {
            uint32_t ah[2][4], al[2][4];
            #pragma unroll
            for (int mr = 0; mr < 2; mr++) {
                int base = SM_P + (m0 + mr * 16 + gr) * P_STRIDE
                         + (c2 * 64 + ks * 16 + cl * 2) * 2;
                ah[mr][0] = *(const uint32_t*)(smem + base);
                ah[mr][1] = *(const uint32_t*)(smem + base + 8 * P_STRIDE);
                ah[mr][2] = *(const uint32_t*)(smem + base + 16);
                ah[mr][3] = *(const uint32_t*)(smem + base + 8 * P_STRIDE + 16);
                al[mr][0] = *(const uint32_t*)(smem + base + P_PLANE);
                al[mr][1] = *(const uint32_t*)(smem + base + P_PLANE + 8 * P_STRIDE);
                al[mr][2] = *(const uint32_t*)(smem + base + P_PLANE + 16);
                al[mr][3] = *(const uint32_t*)(smem + base + P_PLANE + 8 * P_STRIDE + 16);
            }
            #pragma unroll
            for (int mat = 0; mat < 2; mat++) {
                int ph = SM_W + (mat * 2) * W_PLANE, plo = ph + W_PLANE;
                #pragma unroll
                for (int nc = 0; nc < 4; nc++) {
                    int wb = (n0 + nc * 8 + gr) * A_STRIDE + ks * 32 + cl * 4;
                    uint32_t bh0 = *(const uint32_t*)(smem + ph + wb);
                    uint32_t bh1 = *(const uint32_t*)(smem + ph + wb + 16);
                    uint32_t bl0 = *(const uint32_t*)(smem + plo + wb);
                    uint32_t bl1 = *(const uint32_t*)(smem + plo + wb + 16);
                    #pragma unroll
                    for (int mr = 0; mr < 2; mr++) {
                        float* cc = mat ? accB[mr][nc] : accA[mr][nc];
                        mma16816(cc, ah[mr], bh0, bh1);
                        mma16816(cc, ah[mr], bl0, bl1);
                        mma16816(cc, al[mr], bh0, bh1);
                    }
                }
            }
        }
    }

    // ======== epilogue 2: residual + skip accumulator update ========
    {
        const float* bSp = (const float*)(smem + SM_BS);
        const float* bRp = (const float*)(smem + SM_BR);
        #pragma unroll
        for (int mr = 0; mr < 2; mr++)
            #pragma unroll
            for (int nc = 0; nc < 4; nc++) {
                int m = m0 + mr * 16 + gr, n = n0 + nc * 8 + cl * 2;
                #pragma unroll
                for (int h = 0; h < 2; h++) {
                    size_t gi = (size_t)(t0 + m + h * 8) * RC + n;
                    float2 rold = *(const float2*)&rin[gi];
                    float2 rnew;
                    rnew.x = rold.x + accB[mr][nc][h * 2 + 0] + bRp[n];
                    rnew.y = rold.y + accB[mr][nc][h * 2 + 1] + bRp[n + 1];
                    *(float2*)&rout[gi] = rnew;
                    float2 s;
                    s.x = accA[mr][nc][h * 2 + 0] + bSp[n];
                    s.y = accA[mr][nc][h * 2 + 1] + bSp[n + 1];
                    if (!first) {
                        float2 o = *(const float2*)&oacc[gi];
                        s.x += o.x; s.y += o.y;
                    }
                    *(float2*)&oacc[gi] = s;
                }
            }
    }
}

// ---------------- fused skip stack (unchanged) ----------------
#define SK_W0   0
#define SK_WR   4096
#define SK_WF   35840
#define SK_B0   44032
#define SK_BR   44064
#define SK_BF   45056
#define SK_TOT  45312

__global__ __launch_bounds__(512)
void k_skip(const float* __restrict__ oacc,
            const float* __restrict__ w0, const float* __restrict__ b0,
            const float* __restrict__ wr, const float* __restrict__ br,
            const float* __restrict__ wf, const float* __restrict__ bf,
            float* __restrict__ y)
{
    extern __shared__ float sm[];
    const int tid = threadIdx.x;
    for (int i = tid; i < 4096;  i += 512) sm[SK_W0 + i] = w0[i];
    for (int i = tid; i < 31744; i += 512) sm[SK_WR + i] = wr[i];
    for (int i = tid; i < 8192;  i += 512) sm[SK_WF + i] = wf[i];
    for (int i = tid; i < 32;    i += 512) sm[SK_B0 + i] = b0[i];
    for (int i = tid; i < 992;   i += 512) sm[SK_BR + i] = br[i];
    for (int i = tid; i < 256;   i += 512) sm[SK_BF + i] = bf[i];
    __syncthreads();

    const int row = blockIdx.x * 512 + tid;
    float h[32];
    #pragma unroll
    for (int c = 0; c < 32; c++) h[c] = sm[SK_B0 + c];

    const float4* in4 = (const float4*)(oacc + (size_t)row * RC);
    const float4* w0_4 = (const float4*)(sm + SK_W0);
    #pragma unroll 4
    for (int k4 = 0; k4 < 32; k4++) {
        float4 x = __ldg(&in4[k4]);
        x.x = fmaxf(x.x, 0.f); x.y = fmaxf(x.y, 0.f);
        x.z = fmaxf(x.z, 0.f); x.w = fmaxf(x.w, 0.f);
        #pragma unroll
        for (int j = 0; j < 4; j++) {
            float xv = comp(x, j);
            #pragma unroll
            for (int c4 = 0; c4 < 8; c4++) {
                float4 w = w0_4[(k4 * 4 + j) * 8 + c4];
                h[c4*4+0] += xv * w.x; h[c4*4+1] += xv * w.y;
                h[c4*4+2] += xv * w.z; h[c4*4+3] += xv * w.w;
            }
        }
    }
    #pragma unroll 1
    for (int step = 0; step < 31; step++) {
        float hn[32];
        #pragma unroll
        for (int c = 0; c < 32; c++) hn[c] = sm[SK_BR + step * 32 + c];
        const float4* wr4 = (const float4*)(sm + SK_WR + step * 1024);
        #pragma unroll
        for (int k = 0; k < 32; k++) {
            float xv = fmaxf(h[k], 0.f);
            #pragma unroll
            for (int c4 = 0; c4 < 8; c4++) {
                float4 w = wr4[k * 8 + c4];
                hn[c4*4+0] += xv * w.x; hn[c4*4+1] += xv * w.y;
                hn[c4*4+2] += xv * w.z; hn[c4*4+3] += xv * w.w;
            }
        }
        #pragma unroll
        for (int c = 0; c < 32; c++) h[c] = hn[c];
    }
    float rh[32];
    #pragma unroll
    for (int k = 0; k < 32; k++) rh[k] = fmaxf(h[k], 0.f);
    const float4* wf4 = (const float4*)(sm + SK_WF);
    const float4* bf4 = (const float4*)(sm + SK_BF);
    float* yrow = y + (size_t)row * 256;
    #pragma unroll 1
    for (int g = 0; g < 8; g++) {
        float4 acc[8];
        #pragma unroll
        for (int c4 = 0; c4 < 8; c4++) acc[c4] = bf4[g * 8 + c4];
        #pragma unroll
        for (int k = 0; k < 32; k++) {
            float xv = rh[k];
            #pragma unroll
            for (int c4 = 0; c4 < 8; c4++) {
                float4 w = wf4[k * 64 + g * 8 + c4];
                acc[c4].x += xv * w.x; acc[c4].y += xv * w.y;
                acc[c4].z += xv * w.z; acc[c4].w += xv * w.w;
            }
        }
        #pragma unroll
        for (int c4 = 0; c4 < 8; c4++)
            *(float4*)&yrow[g * 32 + c4 * 4] = acc[c4];
    }
}

// ---------------- launch ----------------
extern "C" void kernel_launch(void* const* d_in, const int* in_sizes, int n_in,
                              void* d_out, int out_size)
{
    const float* X      = (const float*)d_in[0];
    const float* init_w = (const float*)d_in[1];
    const float* init_b = (const float*)d_in[2];
    const float* f_w    = (const float*)d_in[3];
    const float* f_b    = (const float*)d_in[4];
    const float* g_w    = (const float*)d_in[5];
    const float* g_b    = (const float*)d_in[6];
    const float* skip_w = (const float*)d_in[7];
    const float* skip_b = (const float*)d_in[8];
    const float* res_w  = (const float*)d_in[9];
    const float* res_b  = (const float*)d_in[10];
    const float* sk0_w  = (const float*)d_in[11];
    const float* sk0_b  = (const float*)d_in[12];
    const float* skr_w  = (const float*)d_in[13];
    const float* skr_b  = (const float*)d_in[14];
    const float* fin_w  = (const float*)d_in[15];
    const float* fin_b  = (const float*)d_in[16];

    float *r0, *r1, *oa;
    __nv_bfloat16* wpre;
    cudaGetSymbolAddress((void**)&r0, g_res0);
    cudaGetSymbolAddress((void**)&r1, g_res1);
    cudaGetSymbolAddress((void**)&oa, g_skipacc);
    cudaGetSymbolAddress((void**)&wpre, g_wprep);

    const int SM_INIT  = 96 * 64 * 4 + 64 * 128 * 4;   // 57344
    const int SM_SKIP  = SK_TOT * 4;                   // 181248
    cudaFuncSetAttribute(k_init,      cudaFuncAttributeMaxDynamicSharedMemorySize, SM_INIT);
    cudaFuncSetAttribute(k_layer_mma, cudaFuncAttributeMaxDynamicSharedMemorySize, SM_TOTAL);
    cudaFuncSetAttribute(k_skip,      cudaFuncAttributeMaxDynamicSharedMemorySize, SM_SKIP);

    k_prep<<<NLAYERS * 12, 256>>>(f_w, g_w, skip_w, res_w);
    k_init<<<M_ROWS / 64, 256, SM_INIT>>>(X, init_w, init_b, r0);

    const float* rin = r0;
    float* rout = r1;
    for (int i = 0; i < NLAYERS; i++) {
        k_layer_mma<<<M_ROWS / 128, 512, SM_TOTAL>>>(
            rin, rout,
            wpre + (size_t)i * 12 * 2 * 8192,
            f_b + (size_t)i * RC, g_b + (size_t)i * RC,
            skip_b + (size_t)i * RC, res_b + (size_t)i * RC,
            oa, H_DIL[i], (i == 0) ? 1 : 0);
        const float* t = rin; rin = rout; rout = (float*)t;
    }

    k_skip<<<M_ROWS / 512, 512, SM_SKIP>>>(oa, sk0_w, sk0_b, skr_w, skr_b,
                                           fin_w, fin_b, (float*)d_out);
}